// round 11
// baseline (speedup 1.0000x reference)
#include <cuda_runtime.h>
#include <math.h>

#define N_IMG   512
#define N_ANG   25
#define N_DET   512
#define N_SAMP  1024
#define N_RAYS  (N_ANG * N_DET)
#define TB      514              // bordered coords: gq = g0+1, fq = f0+1, in [0, 513]
#define TBH     257              // row-pair count

#define SRC_DIST 512.0f
#define DET_DIST 512.0f
#define DET_SPACING 3.0f

// Row-pair interleaved differential quad tables (see R10):
// slot(gq,fq) = ((gq>>1)*TB + fq)*2 + (gq&1)  -> 128B line = 4(f) x 2(g) footprint.
// Payload: .x=v00 .y=v01-v00 .z=v10-v00 .w=v11-v10-v01+v00 ; bilinear = .x+wf*.y+wg*(.z+wf*.w)
__device__ float4 g_quadB [TBH * TB * 2];
__device__ float4 g_quadBT[TBH * TB * 2];

__device__ __forceinline__ float4 diffquad(float a, float b, float c, float d) {
    return make_float4(a, b - a, c - a, (d - c) - (b - a));
}

__device__ __forceinline__ int slot_of(int gq, int fq) {
    return ((gq >> 1) * TB + fq) * 2 + (gq & 1);
}

__global__ __launch_bounds__(256)
void prep_kernel(const float* __restrict__ img) {
    __shared__ float sm[33][33];
    int tx = threadIdx.x;              // 0..31
    int ty = threadIdx.y;              // 0..7
    int fbase = blockIdx.x * 32 - 1;
    int gbase = blockIdx.y * 32 - 1;
    int z = blockIdx.z;

    bool interior = (blockIdx.x > 0) & (blockIdx.y > 0) &
                    (fbase + 32 < N_IMG) & (gbase + 32 < N_IMG);

    if (interior) {
        if (z == 0) {
            #pragma unroll
            for (int a = ty; a < 33; a += 8) {
                const float* rp = img + (gbase + a) * N_IMG + fbase;
                sm[a][tx] = rp[tx];
                if (tx == 0) sm[a][32] = rp[32];
            }
        } else {
            #pragma unroll
            for (int b = ty; b < 33; b += 8) {
                const float* rp = img + (fbase + b) * N_IMG + gbase;
                sm[tx][b] = rp[tx];
                if (tx == 0) sm[32][b] = rp[32];
            }
        }
    } else {
        if (z == 0) {
            for (int a = ty; a < 33; a += 8) {
                int r = gbase + a;
                bool rok = (r >= 0) & (r < N_IMG);
                for (int b = tx; b < 33; b += 32) {
                    int c = fbase + b;
                    sm[a][b] = (rok && c >= 0 && c < N_IMG) ? img[r * N_IMG + c] : 0.0f;
                }
            }
        } else {
            for (int b = ty; b < 33; b += 8) {
                int r = fbase + b;
                bool rok = (r >= 0) & (r < N_IMG);
                for (int a = tx; a < 33; a += 32) {
                    int c = gbase + a;
                    sm[a][b] = (rok && c >= 0 && c < N_IMG) ? img[r * N_IMG + c] : 0.0f;
                }
            }
        }
    }
    __syncthreads();

    float4* __restrict__ dst = z ? g_quadBT : g_quadB;
    int fq = blockIdx.x * 32 + tx;
    if (fq < TB) {
        #pragma unroll
        for (int gg = ty; gg < 32; gg += 8) {
            int gq = blockIdx.y * 32 + gg;
            if (gq < TB)
                dst[slot_of(gq, fq)] = diffquad(sm[gg][tx], sm[gg][tx + 1],
                                                sm[gg + 1][tx], sm[gg + 1][tx + 1]);
        }
    }
}

// shrink [u0,u1] so that p + u*v stays within [lo, hi]
__device__ __forceinline__ void clip_axis(float p, float v, float lo, float hi,
                                          float& u0, float& u1) {
    if (fabsf(v) < 1e-12f) {
        if (p < lo || p > hi) { u0 = 1e30f; u1 = -1e30f; }
    } else {
        float inv = __fdividef(1.0f, v);
        float a = (lo - p) * inv;
        float b = (hi - p) * inv;
        float mn = fminf(a, b), mx = fmaxf(a, b);
        u0 = fmaxf(u0, mn);
        u1 = fminf(u1, mx);
    }
}

// Warp layout: each warp = (ray pair, half of sample range).
//   pair  = blockIdx.x*4 + (warp>>1)   -> detectors 2*(pair%256), +1 of angle pair/256
//   k     = warp&1                      -> which contiguous half of the sample range
//   lanes 0-15 -> ray 0 of pair, lanes 16-31 -> ray 1; 16 CONSECUTIVE samples per load.
__global__ __launch_bounds__(256)
void fanbeam_kernel(float* __restrict__ out) {
    __shared__ float partial[16];      // [warp][ray_sel]

    int w    = threadIdx.x >> 5;
    int lane = threadIdx.x & 31;
    int sub  = lane & 15;
    int rsel = lane >> 4;
    int k    = w & 1;

    int pair = blockIdx.x * 4 + (w >> 1);
    int a  = pair >> 8;                // / 256 pairs per angle
    int d  = ((pair & 255) << 1) + rsel;

    float beta = (float)a * (2.0f * 3.14159265358979323846f / (float)N_ANG);
    float s, c;
    sincosf(beta, &s, &c);

    float t  = ((float)d - (float)(N_DET - 1) * 0.5f) * DET_SPACING;
    float sx = -SRC_DIST * s;
    float sy =  SRC_DIST * c;
    float dx = t * c + DET_DIST * s - sx;
    float dy = t * s - DET_DIST * c - sy;
    float seg = sqrtf(dx * dx + dy * dy);

    const float half  = (float)(N_IMG - 1) * 0.5f;   // 255.5
    const float inv_s = 1.0f / (float)N_SAMP;
    float cA = sx + half;
    float rA = half - sy;

    float dxs = dx * inv_s;
    float dys = -dy * inv_s;
    float cA0 = fmaf(0.5f, dxs, cA);
    float rA0 = fmaf(0.5f, dys, rA);

    // orientation: fast axis = larger per-sample step (warp-uniform: both rays
    // of a pair have nearly identical directions; use ray 0's choice so the
    // branch is uniform). Compute both candidates, select by ray-0 criterion
    // broadcast across the warp.
    bool swp_self = fabsf(dys) > fabsf(dxs);
    bool swp = __shfl_sync(0xffffffffu, (int)swp_self, 0);
    float fA0 = (swp ? rA0 : cA0) + 1.0f;   // table coords
    float fds = swp ? dys : dxs;
    float gA0 = (swp ? cA0 : rA0) + 1.0f;
    float gds = swp ? dxs : dys;

    // clip coords to [-0.998, 512] -> floor in [-1, 512]
    float u0 = 0.0f, u1 = 1.0f;
    clip_axis(cA,  dx, -0.998f, 512.0f, u0, u1);
    clip_axis(rA, -dy, -0.998f, 512.0f, u0, u1);

    int s0, s1;
    if (u0 <= u1) {
        s0 = max(0,          (int)ceilf (u0 * (float)N_SAMP - 0.5f));
        s1 = min(N_SAMP - 1, (int)floorf(u1 * (float)N_SAMP - 0.5f));
    } else {
        s0 = 0; s1 = -1;                   // dead ray -> empty range
    }

    int len = s1 - s0 + 1;  if (len < 0) len = 0;
    int h   = (len + 1) >> 1;
    int beg = s0 + k * h;
    int end = min(s1, s0 + (k + 1) * h - 1);

    // ---- setup done; wait for prep_kernel's tables (PDL) ----
#if __CUDA_ARCH__ >= 900
    cudaGridDependencySynchronize();
#endif

    const float4* __restrict__ tab = swp ? g_quadBT : g_quadB;

    float acc = 0.0f;
    #pragma unroll 4
    for (int i = beg + sub; i <= end; i += 16) {
        float fi = (float)i;
        float fp = fmaf(fi, fds, fA0);
        float gp = fmaf(fi, gds, gA0);
        float fqf = floorf(fp);
        float gqf = floorf(gp);
        float wf = fp - fqf;
        float wg = gp - gqf;
        int fq = (int)fqf;
        int gq = (int)gqf;
        int slot = ((gq >> 1) * TB + fq) * 2 + (gq & 1);
        float4 q = __ldg(tab + slot);
        float u1v = fmaf(wf, q.y, q.x);
        float u2v = fmaf(wf, q.w, q.z);
        acc      += fmaf(wg, u2v, u1v);
    }

    acc *= seg * inv_s;   // per-ray scale before reduction

    // reduce within each 16-lane segment
    #pragma unroll
    for (int o = 8; o > 0; o >>= 1)
        acc += __shfl_down_sync(0xffffffffu, acc, o, 16);

    if (sub == 0)
        partial[w * 2 + rsel] = acc;
    __syncthreads();

    // 8 rays per block: combine the two half-range warps and store
    if (threadIdx.x < 8) {
        int pl = threadIdx.x >> 1;     // pair within block (0..3)
        int rs = threadIdx.x & 1;
        float v = partial[(pl * 2) * 2 + rs] + partial[(pl * 2 + 1) * 2 + rs];
        int gpair = blockIdx.x * 4 + pl;
        int aa = gpair >> 8;
        int dd = ((gpair & 255) << 1) + rs;
        out[aa * N_DET + dd] = v;
    }
}

extern "C" void kernel_launch(void* const* d_in, const int* in_sizes, int n_in,
                              void* d_out, int out_size) {
    (void)in_sizes; (void)n_in; (void)out_size;
    const float* img = (const float*)d_in[0];
    float* out = (float*)d_out;

    dim3 tb(32, 8);
    dim3 tg(17, 17, 2);
    prep_kernel<<<tg, tb>>>(img);

    cudaLaunchConfig_t cfg = {};
    cfg.gridDim  = dim3(1600, 1, 1);   // 4 pairs (8 rays) per block
    cfg.blockDim = dim3(256, 1, 1);
    cfg.dynamicSmemBytes = 0;
    cudaLaunchAttribute attr[1];
    attr[0].id = cudaLaunchAttributeProgrammaticStreamSerialization;
    attr[0].val.programmaticStreamSerializationAllowed = 1;
    cfg.attrs = attr;
    cfg.numAttrs = 1;
    cudaLaunchKernelEx(&cfg, fanbeam_kernel, out);
}

// round 12
// speedup vs baseline: 1.0345x; 1.0345x over previous
#include <cuda_runtime.h>
#include <math.h>

#define N_IMG   512
#define N_ANG   25
#define N_DET   512
#define N_SAMP  1024
#define N_RAYS  (N_ANG * N_DET)
#define TB      514              // bordered coords: gq = g0+1, fq = f0+1, in [0, 513]
#define TBH     257              // g pair-row count

#define SRC_DIST 512.0f
#define DET_DIST 512.0f
#define DET_SPACING 3.0f

// Row-pair interleaved differential quad tables:
// slot(gq,fq) = ((gq>>1)*TB + fq)*2 + (gq&1)  -> 128B line = 4(f) x 2(g) footprint.
// Payload: .x=v00 .y=v01-v00 .z=v10-v00 .w=v11-v10-v01+v00 ; bilinear = .x+wf*.y+wg*(.z+wf*.w)
//  g_quadB : g = image row, f = image col ; g_quadBT: g = col, f = row (v(g,f)=img[f][g])
__device__ float4 g_quadB [TBH * TB * 2];
__device__ float4 g_quadBT[TBH * TB * 2];

__device__ __forceinline__ float4 diffquad(float a, float b, float c, float d) {
    return make_float4(a, b - a, c - a, (d - c) - (b - a));
}

// Tile: 32 g x 32 f of quad entries per block. smem holds the needed 33x33
// source patch: sm[a][b] = v(gbase-1+a, fbase-1+b) with zero padding.
// Store mapping is lane->slot IDENTITY-contiguous: lane l covers
// (f_local = h*16 + (l>>1), parity = l&1), so each STG.128 writes 32
// consecutive slots = 512B fully coalesced.
__global__ __launch_bounds__(256)
void prep_kernel(const float* __restrict__ img) {
    __shared__ float sm[33][33];
    int tx = threadIdx.x;              // 0..31
    int ty = threadIdx.y;              // 0..7
    int fbase = blockIdx.x * 32;       // fq tile base
    int gbase = blockIdx.y * 32;       // gq tile base (16 pair-rows)
    int z = blockIdx.z;

    // source coords: v(g,f) needed for g in [gbase-1, gbase+31], f in [fbase-1, fbase+31]
    int gs = gbase - 1, fs = fbase - 1;
    bool interior = (gs >= 0) & (fs >= 0) & (gs + 32 < N_IMG) & (fs + 32 < N_IMG);

    if (interior) {
        if (z == 0) {
            #pragma unroll
            for (int a = ty; a < 33; a += 8) {
                const float* rp = img + (gs + a) * N_IMG + fs;
                sm[a][tx] = rp[tx];
                if (tx == 0) sm[a][32] = rp[32];
            }
        } else {
            #pragma unroll
            for (int b = ty; b < 33; b += 8) {
                const float* rp = img + (fs + b) * N_IMG + gs;
                sm[tx][b] = rp[tx];
                if (tx == 0) sm[32][b] = rp[32];
            }
        }
    } else {
        if (z == 0) {
            for (int a = ty; a < 33; a += 8) {
                int r = gs + a;
                bool rok = (r >= 0) & (r < N_IMG);
                for (int b = tx; b < 33; b += 32) {
                    int c = fs + b;
                    sm[a][b] = (rok && c >= 0 && c < N_IMG) ? img[r * N_IMG + c] : 0.0f;
                }
            }
        } else {
            for (int b = ty; b < 33; b += 8) {
                int r = fs + b;
                bool rok = (r >= 0) & (r < N_IMG);
                for (int a = tx; a < 33; a += 32) {
                    int c = gs + a;
                    sm[a][b] = (rok && c >= 0 && c < N_IMG) ? img[r * N_IMG + c] : 0.0f;
                }
            }
        }
    }
    __syncthreads();

    float4* __restrict__ dst = z ? g_quadBT : g_quadB;

    int p  = tx & 1;                 // g parity handled by this lane
    int fl = tx >> 1;                // f sub-index (0..15)
    int gpair_base = blockIdx.y * 16;

    // 16 pair-rows x 2 f-halves; ty strides the 32 (pl, h) combos
    #pragma unroll
    for (int it = ty; it < 32; it += 8) {
        int pl = it >> 1;            // pair-row 0..15
        int h  = it & 1;             // f half 0..1
        int ff = h * 16 + fl;        // local f 0..31
        int gg = 2 * pl + p;         // local g 0..31
        int fq = fbase + ff;
        int gq = gbase + gg;
        if (fq < TB && gq < TB) {
            float4 q = diffquad(sm[gg][ff], sm[gg][ff + 1],
                                sm[gg + 1][ff], sm[gg + 1][ff + 1]);
            // slot = ((gq>>1)*TB + fq)*2 + p ; consecutive across lanes
            dst[(((gpair_base + pl) * TB) + fq) * 2 + p] = q;
        }
    }
}

// shrink [u0,u1] so that p + u*v stays within [lo, hi]
__device__ __forceinline__ void clip_axis(float p, float v, float lo, float hi,
                                          float& u0, float& u1) {
    if (fabsf(v) < 1e-12f) {
        if (p < lo || p > hi) { u0 = 1e30f; u1 = -1e30f; }
    } else {
        float inv = __fdividef(1.0f, v);
        float a = (lo - p) * inv;
        float b = (hi - p) * inv;
        float mn = fminf(a, b), mx = fmaxf(a, b);
        u0 = fmaxf(u0, mn);
        u1 = fminf(u1, mx);
    }
}

__global__ __launch_bounds__(256)
void fanbeam_kernel(float* __restrict__ out) {
    int gwarp = blockIdx.x * 8 + (threadIdx.x >> 5);
    int lane  = threadIdx.x & 31;

    int a = gwarp >> 9;            // / N_DET (512)
    int d = gwarp & (N_DET - 1);

    float beta = (float)a * (2.0f * 3.14159265358979323846f / (float)N_ANG);
    float s, c;
    sincosf(beta, &s, &c);

    float t  = ((float)d - (float)(N_DET - 1) * 0.5f) * DET_SPACING;
    float sx = -SRC_DIST * s;
    float sy =  SRC_DIST * c;
    float dx = t * c + DET_DIST * s - sx;
    float dy = t * s - DET_DIST * c - sy;
    float seg = sqrtf(dx * dx + dy * dy);

    const float half  = (float)(N_IMG - 1) * 0.5f;   // 255.5
    const float inv_s = 1.0f / (float)N_SAMP;
    float cA = sx + half;          // col(u) = cA + u*dx
    float rA = half - sy;          // row(u) = rA - u*dy

    float dxs = dx * inv_s;
    float dys = -dy * inv_s;
    float cA0 = fmaf(0.5f, dxs, cA);
    float rA0 = fmaf(0.5f, dys, rA);

    // orientation: fast axis = larger per-sample step
    bool swp = fabsf(dys) > fabsf(dxs);
    // shift into table coords (+1) so floor() gives gq,fq >= 0 directly
    float fA0 = (swp ? rA0 : cA0) + 1.0f;
    float fds = swp ? dys : dxs;
    float gA0 = (swp ? cA0 : rA0) + 1.0f;
    float gds = swp ? dxs : dys;

    // single clip: coords in [-0.998, 512] -> floor in [-1, 512]
    float u0 = 0.0f, u1 = 1.0f;
    clip_axis(cA,  dx, -0.998f, 512.0f, u0, u1);
    clip_axis(rA, -dy, -0.998f, 512.0f, u0, u1);

    int s0 = max(0,          (int)ceilf (u0 * (float)N_SAMP - 0.5f));
    int s1 = min(N_SAMP - 1, (int)floorf(u1 * (float)N_SAMP - 0.5f));
    bool live = (u0 <= u1);

    // ---- all setup done; wait for prep_kernel's tables (PDL) ----
#if __CUDA_ARCH__ >= 900
    cudaGridDependencySynchronize();
#endif

    const float4* __restrict__ tab = swp ? g_quadBT : g_quadB;

    float acc = 0.0f;
    if (live) {
        #pragma unroll 4
        for (int i = s0 + lane; i <= s1; i += 32) {
            float fi = (float)i;
            float fp = fmaf(fi, fds, fA0);   // table coords (>= 0)
            float gp = fmaf(fi, gds, gA0);
            float fqf = floorf(fp);
            float gqf = floorf(gp);
            float wf = fp - fqf;
            float wg = gp - gqf;
            int fq = (int)fqf;
            int gq = (int)gqf;
            int slot = ((gq >> 1) * TB + fq) * 2 + (gq & 1);
            float4 q = __ldg(tab + slot);
            float u1v = fmaf(wf, q.y, q.x);
            float u2v = fmaf(wf, q.w, q.z);
            acc      += fmaf(wg, u2v, u1v);
        }
    }

    #pragma unroll
    for (int o = 16; o > 0; o >>= 1)
        acc += __shfl_down_sync(0xffffffffu, acc, o);

    if (lane == 0)
        out[gwarp] = acc * seg * inv_s;
}

extern "C" void kernel_launch(void* const* d_in, const int* in_sizes, int n_in,
                              void* d_out, int out_size) {
    (void)in_sizes; (void)n_in; (void)out_size;
    const float* img = (const float*)d_in[0];
    float* out = (float*)d_out;

    dim3 tb(32, 8);
    dim3 tg(17, 17, 2);
    prep_kernel<<<tg, tb>>>(img);

    cudaLaunchConfig_t cfg = {};
    cfg.gridDim  = dim3(N_RAYS / 8, 1, 1);
    cfg.blockDim = dim3(256, 1, 1);
    cfg.dynamicSmemBytes = 0;
    cudaLaunchAttribute attr[1];
    attr[0].id = cudaLaunchAttributeProgrammaticStreamSerialization;
    attr[0].val.programmaticStreamSerializationAllowed = 1;
    cfg.attrs = attr;
    cfg.numAttrs = 1;
    cudaLaunchKernelEx(&cfg, fanbeam_kernel, out);
}